// round 3
// baseline (speedup 1.0000x reference)
#include <cuda_runtime.h>
#include <math.h>

#define Bsz 256
#define Xd  256
#define Hd  512
#define Rd  128
#define Md  128
#define Td  256
#define XHD 768      // X+H
#define CATD 896     // X+H+R
#define NPRE 2176    // R+4H columns of W_full
#define NG1 640      // R+H
#define ODIM 640

// persistent state / scratch (device globals; no allocation)
__device__ float g_c[Bsz*Hd];
__device__ float g_hmem[Bsz*Md*Rd];
__device__ float g_cc [Bsz*CATD];   // unscaled concat [x, c, h_entry]
__device__ float g_cc2[Bsz*CATD];   // scaled concat
__device__ float g_hent[Bsz*Rd];
__device__ int   g_sel[Bsz];
__device__ float g_fcwT[XHD*Md];    // fc_w transposed (k-major)
__device__ float g_transT[Hd*Rd];   // trans_w transposed

__device__ __forceinline__ float sigf(float v){ return 1.0f/(1.0f+expf(-v)); }

// ---------------- init: transposes + c0 + hmem0 ----------------
__global__ void k_init(const float* __restrict__ fc_w, const float* __restrict__ trans_w,
                       const float* __restrict__ c_bias, const float* __restrict__ hmem_bias)
{
    int idx = blockIdx.x*blockDim.x + threadIdx.x;
    if (idx < Bsz*Md*Rd) {
        g_hmem[idx] = hmem_bias[idx & (Md*Rd-1)];
    }
    if (idx < Bsz*Hd) {
        g_c[idx] = tanhf(c_bias[idx & (Hd-1)]);
    }
    if (idx < XHD*Md) {
        int k = idx >> 7, m = idx & 127;
        g_fcwT[idx] = fc_w[m*XHD + k];
    }
    if (idx < Hd*Rd) {
        int h = idx >> 7, m = idx & 127;
        g_transT[idx] = trans_w[m*Hd + h];
    }
}

// ---------------- gates1 GEMM: cc(256x896) @ W1(896x640), sigmoid-scale into cc2 ----
// BM=32, BN=64, BK=16, 128 threads, thread tile 4x4. grid (8,10)=80 blocks.
__global__ __launch_bounds__(128) void k_gates(const float* __restrict__ W1,
                                               const float* __restrict__ bias1)
{
    __shared__ float As[16][36];   // [k][row], padded
    __shared__ float Bs[16][64];   // [k][col]
    const int tid = threadIdx.x;
    const int rb = blockIdx.x * 32;
    const int nb = blockIdx.y * 64;
    const int tm = tid >> 4;       // 0..7 (rows group of 4)
    const int tn = tid & 15;       // 0..15 (cols group of 4)

    float acc[4][4] = {};

    const int a_row = tid >> 2, a_kq = tid & 3;
    const float* Ap = g_cc + (rb + a_row)*CATD + a_kq*4;
    const float* Bp0 = W1 + (tid>>4)*NG1 + nb + (tid&15)*4;       // k = tid>>4 (0..7)
    const float* Bp1 = Bp0 + 8*NG1;                               // k+8

    float4 pa = *(const float4*)(Ap);
    float4 pb0 = *(const float4*)(Bp0);
    float4 pb1 = *(const float4*)(Bp1);

    for (int kt = 0; kt < CATD/16; kt++) {
        As[a_kq*4+0][a_row]=pa.x; As[a_kq*4+1][a_row]=pa.y;
        As[a_kq*4+2][a_row]=pa.z; As[a_kq*4+3][a_row]=pa.w;
        *(float4*)&Bs[tid>>4][(tid&15)*4] = pb0;
        *(float4*)&Bs[(tid>>4)+8][(tid&15)*4] = pb1;
        __syncthreads();
        if (kt+1 < CATD/16) {
            int k0 = (kt+1)*16;
            pa  = *(const float4*)(Ap + k0);
            pb0 = *(const float4*)(Bp0 + (size_t)k0*NG1);
            pb1 = *(const float4*)(Bp1 + (size_t)k0*NG1);
        }
        #pragma unroll
        for (int kk = 0; kk < 16; kk++) {
            float4 av = *(const float4*)&As[kk][tm*4];
            float4 bv = *(const float4*)&Bs[kk][tn*4];
            float a_[4] = {av.x,av.y,av.z,av.w};
            float b_[4] = {bv.x,bv.y,bv.z,bv.w};
            #pragma unroll
            for (int i=0;i<4;i++)
                #pragma unroll
                for (int j=0;j<4;j++)
                    acc[i][j] = fmaf(a_[i], b_[j], acc[i][j]);
        }
        __syncthreads();
    }
    const int n0 = nb + tn*4;
    float4 bv = *(const float4*)(bias1 + n0);
    #pragma unroll
    for (int i=0;i<4;i++){
        int row = rb + tm*4 + i;
        float4 ccv = *(const float4*)(g_cc + row*CATD + Xd + n0);
        float4 o;
        o.x = ccv.x * sigf(acc[i][0] + bv.x);
        o.y = ccv.y * sigf(acc[i][1] + bv.y);
        o.z = ccv.z * sigf(acc[i][2] + bv.z);
        o.w = ccv.w * sigf(acc[i][3] + bv.w);
        *(float4*)(g_cc2 + row*CATD + Xd + n0) = o;
    }
}

// ---------------- big GEMM with fused LSTM / r epilogue ----------------
// grid (4, 34), 128 threads. y<32: quad tile (cols n, n+512, n+1024, n+1536), LSTM.
// y>=32: om tile (64 contiguous cols at 2048+(y-32)*64), writes r to out.
__global__ __launch_bounds__(128) void k_big(const float* __restrict__ Wf,
                                             const float* __restrict__ bias,
                                             float* __restrict__ out, int t)
{
    __shared__ float As[16][68];
    __shared__ float Bs[16][64];
    const int tid = threadIdx.x;
    const int rb = blockIdx.x * 64;
    const int y = blockIdx.y;
    const bool isOm = (y >= 32);
    const int cb = isOm ? (2048 + (y-32)*64) : y*16;
    const int S  = isOm ? 16 : 512;
    const int ty = tid >> 4;   // 0..7 -> rows ty*8..ty*8+7
    const int tx = tid & 15;   // quad index

    float acc[8][4] = {};

    // A: cc2 tile 64x16, 256 float4; B: W_full tile 16x(4 col-groups of 16)
    const int ar = tid>>2, akq = tid&3;
    const float* Ap0 = g_cc2 + (rb + ar)*CATD + akq*4;
    const float* Ap1 = Ap0 + 32*CATD;
    const int bk = tid>>4, bg = (tid>>2)&3, bq4 = tid&3;
    const float* Bp0 = Wf + (size_t)bk*NPRE + cb + S*bg + bq4*4;
    const float* Bp1 = Bp0 + (size_t)8*NPRE;

    float4 pa0 = *(const float4*)(Ap0);
    float4 pa1 = *(const float4*)(Ap1);
    float4 pb0 = *(const float4*)(Bp0);
    float4 pb1 = *(const float4*)(Bp1);

    for (int kt = 0; kt < CATD/16; kt++) {
        As[akq*4+0][ar]=pa0.x; As[akq*4+1][ar]=pa0.y; As[akq*4+2][ar]=pa0.z; As[akq*4+3][ar]=pa0.w;
        As[akq*4+0][ar+32]=pa1.x; As[akq*4+1][ar+32]=pa1.y; As[akq*4+2][ar+32]=pa1.z; As[akq*4+3][ar+32]=pa1.w;
        Bs[bk  ][(bq4*4+0)*4+bg]=pb0.x; Bs[bk  ][(bq4*4+1)*4+bg]=pb0.y;
        Bs[bk  ][(bq4*4+2)*4+bg]=pb0.z; Bs[bk  ][(bq4*4+3)*4+bg]=pb0.w;
        Bs[bk+8][(bq4*4+0)*4+bg]=pb1.x; Bs[bk+8][(bq4*4+1)*4+bg]=pb1.y;
        Bs[bk+8][(bq4*4+2)*4+bg]=pb1.z; Bs[bk+8][(bq4*4+3)*4+bg]=pb1.w;
        __syncthreads();
        if (kt+1 < CATD/16) {
            int k0 = (kt+1)*16;
            pa0 = *(const float4*)(Ap0 + k0);
            pa1 = *(const float4*)(Ap1 + k0);
            pb0 = *(const float4*)(Bp0 + (size_t)k0*NPRE);
            pb1 = *(const float4*)(Bp1 + (size_t)k0*NPRE);
        }
        #pragma unroll
        for (int kk=0; kk<16; kk++){
            float4 b4 = *(const float4*)&Bs[kk][tx*4];
            float4 a0 = *(const float4*)&As[kk][ty*8];
            float4 a1 = *(const float4*)&As[kk][ty*8+4];
            float a_[8] = {a0.x,a0.y,a0.z,a0.w,a1.x,a1.y,a1.z,a1.w};
            float b_[4] = {b4.x,b4.y,b4.z,b4.w};
            #pragma unroll
            for (int i=0;i<8;i++)
                #pragma unroll
                for (int g=0; g<4; g++)
                    acc[i][g] = fmaf(a_[i], b_[g], acc[i][g]);
        }
        __syncthreads();
    }

    if (!isOm) {
        const int n = cb + tx;
        const float bi = bias[n], bj = bias[n+512], bf = bias[n+1024], bo = bias[n+1536];
        #pragma unroll
        for (int i=0;i<8;i++){
            int row = rb + ty*8 + i;
            float c_old = g_c[row*Hd + n];
            float iv = acc[i][0]+bi, jv = acc[i][1]+bj, fv = acc[i][2]+bf, ov = acc[i][3]+bo;
            float nc = tanhf(c_old*sigf(fv + 1.0f) + sigf(iv)*tanhf(jv));
            g_c[row*Hd + n] = nc;
            out[(size_t)t*Bsz*ODIM + (size_t)row*ODIM + n] = nc * sigf(ov);
        }
    } else {
        #pragma unroll
        for (int g=0; g<4; g++){
            int mcol = (cb - 2048) + tx + 16*g;
            float bm = bias[2048 + mcol];
            #pragma unroll
            for (int i=0;i<8;i++){
                int row = rb + ty*8 + i;
                float rv = g_hent[row*Rd + mcol] * sigf(acc[i][g] + bm);
                out[(size_t)t*Bsz*ODIM + (size_t)row*ODIM + Hd + mcol] = rv;
            }
        }
    }
}

// ---------------- tail: wv + hmem scatter (step t) fused with head/argmax/gather (step t+1)
// grid 64 blocks x 256 threads; each block owns 4 batch rows. t in [-1, T-2].
__global__ __launch_bounds__(256) void k_tail(const float* __restrict__ x,
                                              const float* __restrict__ noise,
                                              const float* __restrict__ fc_b,
                                              const float* __restrict__ trans_b,
                                              int t)
{
    __shared__ float s_cat[4][XHD];      // [x_{t+1}(256) | c(512)]
    __shared__ float s_hp[2][4][Md];     // head partials (k-halves)
    __shared__ int   s_sel[4], s_selold[4];
    const int tid = threadIdx.x;
    const int warp = tid >> 5, lane = tid & 31;
    const int b0 = blockIdx.x * 4;
    const int tn = t + 1;

    { int r = tid >> 6, c = tid & 63;
      *(float4*)&s_cat[r][c*4] =
        *(const float4*)(x + ((size_t)tn*Bsz + b0 + r)*Xd + c*4); }
    #pragma unroll
    for (int j=0;j<2;j++){ int i = tid + 256*j; int r = i>>7, c = i&127;
      *(float4*)&s_cat[r][Xd + c*4] = *(const float4*)(g_c + (b0+r)*Hd + c*4); }
    if (tid < 4) s_selold[tid] = g_sel[b0+tid];
    __syncthreads();

    // Phase A: head partials. 8 warps = (row 0..3) x (k-half 0..1).
    {
        int r = warp & 3, half = warp >> 2;
        float4 acc = {0.f,0.f,0.f,0.f};
        const int k0 = half*384;
        for (int k = k0; k < k0+384; k++){
            float a = s_cat[r][k];
            float4 w4 = *(const float4*)(g_fcwT + (size_t)k*Md + lane*4);
            acc.x = fmaf(a,w4.x,acc.x); acc.y = fmaf(a,w4.y,acc.y);
            acc.z = fmaf(a,w4.z,acc.z); acc.w = fmaf(a,w4.w,acc.w);
        }
        *(float4*)&s_hp[half][r][lane*4] = acc;
    }
    __syncthreads();

    // Phase B: warps 0-3 -> wv (if t>=0); warps 4-7 -> gumbel + argmax.
    float4 wv = {0.f,0.f,0.f,0.f};
    if (warp < 4) {
        if (t >= 0) {
            int r = warp;
            for (int k=0;k<Hd;k++){
                float a = s_cat[r][Xd+k];
                float4 w4 = *(const float4*)(g_transT + (size_t)k*Rd + lane*4);
                wv.x = fmaf(a,w4.x,wv.x); wv.y = fmaf(a,w4.y,wv.y);
                wv.z = fmaf(a,w4.z,wv.z); wv.w = fmaf(a,w4.w,wv.w);
            }
            float4 tb = *(const float4*)(trans_b + lane*4);
            wv.x += tb.x; wv.y += tb.y; wv.z += tb.z; wv.w += tb.w;
        }
    } else {
        int r = warp - 4;
        float4 h0 = *(const float4*)&s_hp[0][r][lane*4];
        float4 h1 = *(const float4*)&s_hp[1][r][lane*4];
        float4 fb = *(const float4*)(fc_b + lane*4);
        float4 nz = *(const float4*)(noise + ((size_t)tn*Bsz + b0 + r)*Md + lane*4);
        float v[4];
        v[0] = h0.x+h1.x+fb.x - logf(1e-20f - logf(1e-20f + nz.x));
        v[1] = h0.y+h1.y+fb.y - logf(1e-20f - logf(1e-20f + nz.y));
        v[2] = h0.z+h1.z+fb.z - logf(1e-20f - logf(1e-20f + nz.z));
        v[3] = h0.w+h1.w+fb.w - logf(1e-20f - logf(1e-20f + nz.w));
        float best = v[0]; int bi = lane*4;
        #pragma unroll
        for (int c=1;c<4;c++) if (v[c] > best){ best = v[c]; bi = lane*4+c; }
        #pragma unroll
        for (int off=16; off; off>>=1){
            float ov = __shfl_xor_sync(0xffffffffu, best, off);
            int   oi = __shfl_xor_sync(0xffffffffu, bi,   off);
            if (ov > best || (ov == best && oi < bi)){ best = ov; bi = oi; }
        }
        if (lane == 0) s_sel[r] = bi;
    }
    __syncthreads();

    // Phase C: hmem row write (before gather may read same row)
    if (warp < 4 && t >= 0) {
        int r = warp;
        int idx = (t < Md) ? t : s_selold[r];
        *(float4*)(g_hmem + ((size_t)(b0+r)*Md + idx)*Rd + lane*4) = wv;
    }
    __syncthreads();

    // Phase D: gather h_entry for t+1, write cc / cc2 / sel
    if (warp < 4) {
        int r = warp;
        int sel = s_sel[r];
        float4 h4 = *(const float4*)(g_hmem + ((size_t)(b0+r)*Md + sel)*Rd + lane*4);
        *(float4*)(g_hent + (b0+r)*Rd + lane*4) = h4;
        *(float4*)(g_cc + (b0+r)*CATD + XHD + lane*4) = h4;
        if (lane == 0) g_sel[b0+r] = sel;
    }
    { int r = tid>>6, c = tid&63;
      float4 xv = *(const float4*)&s_cat[r][c*4];
      *(float4*)(g_cc  + (b0+r)*CATD + c*4) = xv;
      *(float4*)(g_cc2 + (b0+r)*CATD + c*4) = xv; }
    #pragma unroll
    for (int j=0;j<2;j++){ int i = tid + 256*j; int r = i>>7, c = i&127;
      *(float4*)(g_cc + (b0+r)*CATD + Xd + c*4) = *(const float4*)&s_cat[r][Xd + c*4]; }
}

extern "C" void kernel_launch(void* const* d_in, const int* in_sizes, int n_in,
                              void* d_out, int out_size)
{
    const float* x       = (const float*)d_in[0];
    const float* noise   = (const float*)d_in[1];
    const float* W_full  = (const float*)d_in[2];
    const float* bias    = (const float*)d_in[3];
    const float* W_full1 = (const float*)d_in[4];
    const float* bias1   = (const float*)d_in[5];
    const float* fc_w    = (const float*)d_in[6];
    const float* fc_b    = (const float*)d_in[7];
    const float* trans_w = (const float*)d_in[8];
    const float* trans_b = (const float*)d_in[9];
    const float* c_bias  = (const float*)d_in[10];
    const float* hmem_b  = (const float*)d_in[11];
    float* out = (float*)d_out;

    const int initN = Bsz*Md*Rd;
    k_init<<<(initN + 255)/256, 256>>>(fc_w, trans_w, c_bias, hmem_b);
    k_tail<<<64, 256>>>(x, noise, fc_b, trans_b, -1);   // prologue: head/argmax for t=0
    for (int t = 0; t < Td; t++){
        k_gates<<<dim3(8,10), 128>>>(W_full1, bias1);
        k_big  <<<dim3(4,34), 128>>>(W_full, bias, out, t);
        if (t < Td-1) k_tail<<<64, 256>>>(x, noise, fc_b, trans_b, t);
    }
}

// round 4
// speedup vs baseline: 1.0304x; 1.0304x over previous
#include <cuda_runtime.h>
#include <math.h>

#define Bsz 256
#define Xd  256
#define Hd  512
#define Rd  128
#define Md  128
#define Td  256
#define XHD 768      // X+H
#define CATD 896     // X+H+R
#define NPRE 2176    // R+4H columns of W_full
#define NG1 640      // R+H
#define ODIM 640

// persistent state / scratch (device globals; no allocation)
__device__ float g_c[Bsz*Hd];
__device__ float g_hmem[Bsz*Md*Rd];
__device__ float g_cc [Bsz*CATD];   // unscaled concat [x, c, h_entry]
__device__ float g_cc2[Bsz*CATD];   // scaled concat
__device__ float g_hent[Bsz*Rd];
__device__ int   g_sel[Bsz];
__device__ float g_fcwxT[Xd*Md];    // fc_w x-part transposed (k-major), for Xh GEMM
__device__ float g_wcomb[Hd*256];   // [k][0:128]=fc_w c-part^T, [k][128:256]=trans_w^T
__device__ float g_xh[Td*Bsz*Md];   // precomputed x-part of head (+fc_b)

__device__ __forceinline__ float sigf(float v){ return 1.0f/(1.0f+expf(-v)); }

// ---------------- init: transposes + combined weights + c0 + hmem0 ----------------
__global__ void k_init(const float* __restrict__ fc_w, const float* __restrict__ trans_w,
                       const float* __restrict__ c_bias, const float* __restrict__ hmem_bias)
{
    int idx = blockIdx.x*blockDim.x + threadIdx.x;
    if (idx < Bsz*Md*Rd) {
        g_hmem[idx] = hmem_bias[idx & (Md*Rd-1)];
    }
    if (idx < Bsz*Hd) {
        g_c[idx] = tanhf(c_bias[idx & (Hd-1)]);
    }
    if (idx < Xd*Md) {               // fcwxT[k][m] = fc_w[m][k], k<256
        int k = idx >> 7, m = idx & 127;
        g_fcwxT[idx] = fc_w[m*XHD + k];
    }
    if (idx < Hd*256) {              // wcomb[k][c]
        int k = idx >> 8, c = idx & 255;
        g_wcomb[idx] = (c < 128) ? fc_w[c*XHD + Xd + k]       // c-part of fc head
                                 : trans_w[(c-128)*Hd + k];   // trans_w^T
    }
}

// ---------------- Xh precompute: (T*B, 128) = x(T*B,256) @ fcwxT + fc_b ------------
// 64 rows x 128 cols per block, 256 threads, thread tile 8x4. grid 1024.
__global__ __launch_bounds__(256) void k_xhead(const float* __restrict__ x,
                                               const float* __restrict__ fc_b)
{
    __shared__ float As[16][68];
    __shared__ float Bs[16][128];
    const int tid = threadIdx.x;
    const int rb = blockIdx.x * 64;
    const int tm = tid >> 5;        // 0..7 rows group of 8
    const int tn = tid & 31;        // 0..31 cols group of 4

    float acc[8][4] = {};

    const int ar = tid >> 2, akq = tid & 3;
    const float* Ap = x + (size_t)(rb + ar)*Xd + akq*4;
    const int bk = tid >> 4, bm = tid & 15;
    const float* Bp = g_fcwxT + (size_t)bk*Md + bm*8;

    float4 pa = *(const float4*)Ap;
    float4 pb0 = *(const float4*)(Bp);
    float4 pb1 = *(const float4*)(Bp + 4);

    for (int kt = 0; kt < Xd/16; kt++) {
        As[akq*4+0][ar]=pa.x; As[akq*4+1][ar]=pa.y; As[akq*4+2][ar]=pa.z; As[akq*4+3][ar]=pa.w;
        *(float4*)&Bs[bk][bm*8]   = pb0;
        *(float4*)&Bs[bk][bm*8+4] = pb1;
        __syncthreads();
        if (kt+1 < Xd/16) {
            int k0 = (kt+1)*16;
            pa  = *(const float4*)(Ap + k0);
            pb0 = *(const float4*)(Bp + (size_t)k0*Md);
            pb1 = *(const float4*)(Bp + (size_t)k0*Md + 4);
        }
        #pragma unroll
        for (int kk = 0; kk < 16; kk++) {
            float4 a0 = *(const float4*)&As[kk][tm*8];
            float4 a1 = *(const float4*)&As[kk][tm*8+4];
            float4 bv = *(const float4*)&Bs[kk][tn*4];
            float a_[8] = {a0.x,a0.y,a0.z,a0.w,a1.x,a1.y,a1.z,a1.w};
            float b_[4] = {bv.x,bv.y,bv.z,bv.w};
            #pragma unroll
            for (int i=0;i<8;i++)
                #pragma unroll
                for (int j=0;j<4;j++)
                    acc[i][j] = fmaf(a_[i], b_[j], acc[i][j]);
        }
        __syncthreads();
    }
    float4 fb = *(const float4*)(fc_b + tn*4);
    #pragma unroll
    for (int i=0;i<8;i++){
        int row = rb + tm*8 + i;
        float4 o = { acc[i][0]+fb.x, acc[i][1]+fb.y, acc[i][2]+fb.z, acc[i][3]+fb.w };
        *(float4*)(g_xh + (size_t)row*Md + tn*4) = o;
    }
}

// ---------------- gates1 GEMM: cc(256x896) @ W1(896x640), sigmoid-scale into cc2 ----
// BM=16, BN=64, BK=16, 128 threads, thread tile 2x4, double-buffered. grid (16,10)=160.
__global__ __launch_bounds__(128) void k_gates(const float* __restrict__ W1,
                                               const float* __restrict__ bias1)
{
    __shared__ float As[2][16][18];
    __shared__ float Bs[2][16][64];
    const int tid = threadIdx.x;
    const int rb = blockIdx.x * 16;
    const int nb = blockIdx.y * 64;
    const int tm = tid >> 4;       // 0..7 rows group of 2
    const int tn = tid & 15;       // 0..15 cols group of 4

    float acc[2][4] = {};

    const int ar = tid >> 2, akq = tid & 3;          // ar 0..15 valid for tid<64
    const float* Ap = g_cc + (size_t)(rb + ar)*CATD + akq*4;
    const int bk = tid >> 4, bn4 = tid & 15;
    const float* Bp0 = W1 + (size_t)bk*NG1 + nb + bn4*4;
    const float* Bp1 = Bp0 + (size_t)8*NG1;

    float4 pa = {0,0,0,0};
    if (tid < 64) pa = *(const float4*)Ap;
    float4 pb0 = *(const float4*)Bp0;
    float4 pb1 = *(const float4*)Bp1;

    // store buffer 0
    if (tid < 64){
        As[0][akq*4+0][ar]=pa.x; As[0][akq*4+1][ar]=pa.y;
        As[0][akq*4+2][ar]=pa.z; As[0][akq*4+3][ar]=pa.w;
    }
    *(float4*)&Bs[0][bk  ][bn4*4] = pb0;
    *(float4*)&Bs[0][bk+8][bn4*4] = pb1;
    __syncthreads();

    for (int kt = 0; kt < CATD/16; kt++) {
        const int p = kt & 1;
        if (kt+1 < CATD/16) {
            int k0 = (kt+1)*16;
            if (tid < 64) pa = *(const float4*)(Ap + k0);
            pb0 = *(const float4*)(Bp0 + (size_t)k0*NG1);
            pb1 = *(const float4*)(Bp1 + (size_t)k0*NG1);
        }
        #pragma unroll
        for (int kk = 0; kk < 16; kk++) {
            float a0 = As[p][kk][tm*2];
            float a1 = As[p][kk][tm*2+1];
            float4 bv = *(const float4*)&Bs[p][kk][tn*4];
            acc[0][0]=fmaf(a0,bv.x,acc[0][0]); acc[0][1]=fmaf(a0,bv.y,acc[0][1]);
            acc[0][2]=fmaf(a0,bv.z,acc[0][2]); acc[0][3]=fmaf(a0,bv.w,acc[0][3]);
            acc[1][0]=fmaf(a1,bv.x,acc[1][0]); acc[1][1]=fmaf(a1,bv.y,acc[1][1]);
            acc[1][2]=fmaf(a1,bv.z,acc[1][2]); acc[1][3]=fmaf(a1,bv.w,acc[1][3]);
        }
        if (kt+1 < CATD/16) {
            const int q = p^1;
            if (tid < 64){
                As[q][akq*4+0][ar]=pa.x; As[q][akq*4+1][ar]=pa.y;
                As[q][akq*4+2][ar]=pa.z; As[q][akq*4+3][ar]=pa.w;
            }
            *(float4*)&Bs[q][bk  ][bn4*4] = pb0;
            *(float4*)&Bs[q][bk+8][bn4*4] = pb1;
        }
        __syncthreads();
    }
    const int n0 = nb + tn*4;
    float4 bv = *(const float4*)(bias1 + n0);
    #pragma unroll
    for (int i=0;i<2;i++){
        int row = rb + tm*2 + i;
        float4 ccv = *(const float4*)(g_cc + (size_t)row*CATD + Xd + n0);
        float4 o;
        o.x = ccv.x * sigf(acc[i][0] + bv.x);
        o.y = ccv.y * sigf(acc[i][1] + bv.y);
        o.z = ccv.z * sigf(acc[i][2] + bv.z);
        o.w = ccv.w * sigf(acc[i][3] + bv.w);
        *(float4*)(g_cc2 + (size_t)row*CATD + Xd + n0) = o;
    }
}

// ---------------- big GEMM with fused LSTM / r epilogue ----------------
// 256 threads, 64 rows x 16 quads, thread tile 4 rows x 1 quad (16 acc),
// double-buffered. grid (4, 34). y<32: gate-quad cols; y>=32: om cols -> r.
__global__ __launch_bounds__(256) void k_big(const float* __restrict__ Wf,
                                             const float* __restrict__ bias,
                                             float* __restrict__ out, int t)
{
    __shared__ float As[2][16][68];
    __shared__ float Bs[2][16][64];
    const int tid = threadIdx.x;
    const int rb = blockIdx.x * 64;
    const int y = blockIdx.y;
    const bool isOm = (y >= 32);
    const int cb = isOm ? (2048 + (y-32)*64) : y*16;
    const int S  = isOm ? 16 : 512;
    const int tm = tid >> 4;   // 0..15 rows group of 4
    const int tx = tid & 15;   // quad index

    float acc[4][4] = {};

    const int ar = tid >> 2, akq = tid & 3;              // ar 0..63
    const float* Ap = g_cc2 + (size_t)(rb + ar)*CATD + akq*4;
    const int bk = tid >> 4, bg = (tid >> 2) & 3, bq4 = tid & 3;   // bk 0..15
    const float* Bp = Wf + (size_t)bk*NPRE + cb + S*bg + bq4*4;

    float4 pa = *(const float4*)Ap;
    float4 pb = *(const float4*)Bp;

    As[0][akq*4+0][ar]=pa.x; As[0][akq*4+1][ar]=pa.y;
    As[0][akq*4+2][ar]=pa.z; As[0][akq*4+3][ar]=pa.w;
    Bs[0][bk][(bq4*4+0)*4+bg]=pb.x; Bs[0][bk][(bq4*4+1)*4+bg]=pb.y;
    Bs[0][bk][(bq4*4+2)*4+bg]=pb.z; Bs[0][bk][(bq4*4+3)*4+bg]=pb.w;
    __syncthreads();

    for (int kt = 0; kt < CATD/16; kt++) {
        const int p = kt & 1;
        if (kt+1 < CATD/16) {
            int k0 = (kt+1)*16;
            pa = *(const float4*)(Ap + k0);
            pb = *(const float4*)(Bp + (size_t)k0*NPRE);
        }
        #pragma unroll
        for (int kk=0; kk<16; kk++){
            float4 av = *(const float4*)&As[p][kk][tm*4];
            float4 bv = *(const float4*)&Bs[p][kk][tx*4];
            float a_[4] = {av.x,av.y,av.z,av.w};
            float b_[4] = {bv.x,bv.y,bv.z,bv.w};
            #pragma unroll
            for (int i=0;i<4;i++)
                #pragma unroll
                for (int g=0; g<4; g++)
                    acc[i][g] = fmaf(a_[i], b_[g], acc[i][g]);
        }
        if (kt+1 < CATD/16) {
            const int q = p^1;
            As[q][akq*4+0][ar]=pa.x; As[q][akq*4+1][ar]=pa.y;
            As[q][akq*4+2][ar]=pa.z; As[q][akq*4+3][ar]=pa.w;
            Bs[q][bk][(bq4*4+0)*4+bg]=pb.x; Bs[q][bk][(bq4*4+1)*4+bg]=pb.y;
            Bs[q][bk][(bq4*4+2)*4+bg]=pb.z; Bs[q][bk][(bq4*4+3)*4+bg]=pb.w;
        }
        __syncthreads();
    }

    if (!isOm) {
        const int n = cb + tx;
        const float bi = bias[n], bj = bias[n+512], bf = bias[n+1024], bo = bias[n+1536];
        #pragma unroll
        for (int i=0;i<4;i++){
            int row = rb + tm*4 + i;
            float c_old = g_c[row*Hd + n];
            float iv = acc[i][0]+bi, jv = acc[i][1]+bj, fv = acc[i][2]+bf, ov = acc[i][3]+bo;
            float nc = tanhf(c_old*sigf(fv + 1.0f) + sigf(iv)*tanhf(jv));
            g_c[row*Hd + n] = nc;
            out[(size_t)t*Bsz*ODIM + (size_t)row*ODIM + n] = nc * sigf(ov);
        }
    } else {
        #pragma unroll
        for (int g=0; g<4; g++){
            int mcol = (cb - 2048) + 16*g + tx;
            float bm = bias[2048 + mcol];
            #pragma unroll
            for (int i=0;i<4;i++){
                int row = rb + tm*4 + i;
                float rv = g_hent[row*Rd + mcol] * sigf(acc[i][g] + bm);
                out[(size_t)t*Bsz*ODIM + (size_t)row*ODIM + Hd + mcol] = rv;
            }
        }
    }
}

// ---------------- tail: [head_c | wv] GEMM (K=512) + argmax + hmem scatter + gather
// grid 64 blocks x 256 threads; 4 batch rows per block. t in [-1, T-2].
__global__ __launch_bounds__(256) void k_tail(const float* __restrict__ x,
                                              const float* __restrict__ noise,
                                              const float* __restrict__ trans_b,
                                              int t)
{
    __shared__ float s_c[4][512];
    __shared__ float s_head[4][132];
    __shared__ float s_wv[4][132];
    __shared__ int   s_sel[4], s_selold[4];
    const int tid = threadIdx.x;
    const int warp = tid >> 5, lane = tid & 31;
    const int b0 = blockIdx.x * 4;
    const int tn = t + 1;

    #pragma unroll
    for (int j=0;j<2;j++){ int i = tid + 256*j; int r = i>>7, cc = i&127;
      *(float4*)&s_c[r][cc*4] = *(const float4*)(g_c + (b0+r)*Hd + cc*4); }
    if (tid < 4) s_selold[tid] = g_sel[b0+tid];
    __syncthreads();

    // GEMM: 4 rows x 256 cols (128 head_c | 128 wv), K=512 from s_c
    {
        const int rg = tid >> 6;          // 0..3 row
        const int c4 = (tid & 63) * 4;    // col group
        float4 acc = {0.f,0.f,0.f,0.f};
        const float* wp = g_wcomb + c4;
        #pragma unroll 4
        for (int k = 0; k < Hd; k++){
            float a = s_c[rg][k];
            float4 w = *(const float4*)(wp + (size_t)k*256);
            acc.x = fmaf(a,w.x,acc.x); acc.y = fmaf(a,w.y,acc.y);
            acc.z = fmaf(a,w.z,acc.z); acc.w = fmaf(a,w.w,acc.w);
        }
        if (c4 < 128) {
            float4 xh = *(const float4*)(g_xh + ((size_t)tn*Bsz + b0 + rg)*Md + c4);
            acc.x += xh.x; acc.y += xh.y; acc.z += xh.z; acc.w += xh.w;
            *(float4*)&s_head[rg][c4] = acc;
        } else {
            int m4 = c4 - 128;
            float4 tb = *(const float4*)(trans_b + m4);
            acc.x += tb.x; acc.y += tb.y; acc.z += tb.z; acc.w += tb.w;
            *(float4*)&s_wv[rg][m4] = acc;
        }
    }
    __syncthreads();

    // Phase C: warps 0-3 argmax; warps 4-7 hmem row write (t>=0)
    if (warp < 4) {
        int r = warp;
        float4 hv = *(const float4*)&s_head[r][lane*4];
        float4 nz = *(const float4*)(noise + ((size_t)tn*Bsz + b0 + r)*Md + lane*4);
        float v[4];
        v[0] = hv.x - logf(1e-20f - logf(1e-20f + nz.x));
        v[1] = hv.y - logf(1e-20f - logf(1e-20f + nz.y));
        v[2] = hv.z - logf(1e-20f - logf(1e-20f + nz.z));
        v[3] = hv.w - logf(1e-20f - logf(1e-20f + nz.w));
        float best = v[0]; int bi = lane*4;
        #pragma unroll
        for (int c=1;c<4;c++) if (v[c] > best){ best = v[c]; bi = lane*4+c; }
        #pragma unroll
        for (int off=16; off; off>>=1){
            float ov = __shfl_xor_sync(0xffffffffu, best, off);
            int   oi = __shfl_xor_sync(0xffffffffu, bi,   off);
            if (ov > best || (ov == best && oi < bi)){ best = ov; bi = oi; }
        }
        if (lane == 0) s_sel[r] = bi;
    } else if (t >= 0) {
        int r = warp - 4;
        float4 wv = *(const float4*)&s_wv[r][lane*4];
        int idx = (t < Md) ? t : s_selold[r];
        *(float4*)(g_hmem + ((size_t)(b0+r)*Md + idx)*Rd + lane*4) = wv;
    }
    __syncthreads();

    // Phase D: gather h_entry for t+1, write cc / cc2 / sel
    if (warp < 4) {
        int r = warp;
        int sel = s_sel[r];
        float4 h4 = *(const float4*)(g_hmem + ((size_t)(b0+r)*Md + sel)*Rd + lane*4);
        *(float4*)(g_hent + (b0+r)*Rd + lane*4) = h4;
        *(float4*)(g_cc + (size_t)(b0+r)*CATD + XHD + lane*4) = h4;
        if (lane == 0) g_sel[b0+r] = sel;
    }
    { int r = tid>>6, cc = tid&63;
      float4 xv = *(const float4*)(x + ((size_t)tn*Bsz + b0 + r)*Xd + cc*4);
      *(float4*)(g_cc  + (size_t)(b0+r)*CATD + cc*4) = xv;
      *(float4*)(g_cc2 + (size_t)(b0+r)*CATD + cc*4) = xv; }
    #pragma unroll
    for (int j=0;j<2;j++){ int i = tid + 256*j; int r = i>>7, cc = i&127;
      *(float4*)(g_cc + (size_t)(b0+r)*CATD + Xd + cc*4) = *(const float4*)&s_c[r][cc*4]; }
}

extern "C" void kernel_launch(void* const* d_in, const int* in_sizes, int n_in,
                              void* d_out, int out_size)
{
    const float* x       = (const float*)d_in[0];
    const float* noise   = (const float*)d_in[1];
    const float* W_full  = (const float*)d_in[2];
    const float* bias    = (const float*)d_in[3];
    const float* W_full1 = (const float*)d_in[4];
    const float* bias1   = (const float*)d_in[5];
    const float* fc_w    = (const float*)d_in[6];
    const float* fc_b    = (const float*)d_in[7];
    const float* trans_w = (const float*)d_in[8];
    const float* trans_b = (const float*)d_in[9];
    const float* c_bias  = (const float*)d_in[10];
    const float* hmem_b  = (const float*)d_in[11];
    float* out = (float*)d_out;

    const int initN = Bsz*Md*Rd;
    k_init<<<(initN + 255)/256, 256>>>(fc_w, trans_w, c_bias, hmem_b);
    k_xhead<<<Td*Bsz/64, 256>>>(x, fc_b);
    k_tail<<<64, 256>>>(x, noise, trans_b, -1);   // prologue: head/argmax for t=0
    for (int t = 0; t < Td; t++){
        k_gates<<<dim3(16,10), 128>>>(W_full1, bias1);
        k_big  <<<dim3(4,34), 256>>>(W_full, bias, out, t);
        if (t < Td-1) k_tail<<<64, 256>>>(x, noise, trans_b, t);
    }
}